// round 16
// baseline (speedup 1.0000x reference)
#include <cuda_runtime.h>
#include <cstdint>

#define NPTS 32768
#define DH 32
#define NH 8
#define BSZ 128
#define NBK 256
#define CHN 24
#define QSTR 36

typedef unsigned long long ull;

__device__ float g_qhat[(size_t)NH * NPTS * QSTR];
__device__ float g_khat[(size_t)NH * NPTS * QSTR];
__device__ float g_v[(size_t)NH * NPTS * DH];
__device__ float g_qh[(size_t)CHN * NPTS];
__device__ float g_kh[(size_t)CHN * NPTS];
__device__ ull   g_keys[(size_t)2 * CHN * NPTS];
__device__ ull   g_keys2[(size_t)2 * CHN * NPTS];
__device__ unsigned g_pmn[CHN * 256];
__device__ unsigned g_pmx[CHN * 256];
__device__ float g_oscr[(size_t)CHN * NPTS * DH];
__device__ float g_dscr[(size_t)CHN * NPTS];

// ---------------- f32x2 helpers ----------------
__device__ __forceinline__ ull pk2(float a, float b) {
    ull r; asm("mov.b64 %0, {%1, %2};" : "=l"(r) : "f"(a), "f"(b)); return r;
}
__device__ __forceinline__ void upk(ull p, float& a, float& b) {
    asm("mov.b64 {%0, %1}, %2;" : "=f"(a), "=f"(b) : "l"(p));
}
__device__ __forceinline__ ull f2fma(ull a, ull b, ull c) {
    ull d; asm("fma.rn.f32x2 %0, %1, %2, %3;" : "=l"(d) : "l"(a), "l"(b), "l"(c)); return d;
}
__device__ __forceinline__ ull f2add(ull a, ull b) {
    ull d; asm("add.rn.f32x2 %0, %1, %2;" : "=l"(d) : "l"(a), "l"(b)); return d;
}
__device__ __forceinline__ ull lo2(float4 v) { return pk2(v.x, v.y); }
__device__ __forceinline__ ull hi2(float4 v) { return pk2(v.z, v.w); }

__device__ __forceinline__ unsigned encf(float f) {
    unsigned u = __float_as_uint(f);
    return (u & 0x80000000u) ? ~u : (u | 0x80000000u);
}
__device__ __forceinline__ float decf(unsigned u) {
    return (u & 0x80000000u) ? __uint_as_float(u ^ 0x80000000u)
                             : __uint_as_float(~u);
}
__device__ __forceinline__ float tf32r(float x) {
    uint32_t u; asm("cvt.rna.tf32.f32 %0, %1;" : "=r"(u) : "f"(x));
    return __uint_as_float(u);
}
#define MMA_TF32(c, a0, a1, a2, a3, b0, b1) \
    asm volatile("mma.sync.aligned.m16n8k8.row.col.f32.tf32.tf32.f32 " \
        "{%0,%1,%2,%3}, {%4,%5,%6,%7}, {%8,%9}, {%0,%1,%2,%3};" \
        : "+f"((c)[0]), "+f"((c)[1]), "+f"((c)[2]), "+f"((c)[3]) \
        : "r"(a0), "r"(a1), "r"(a2), "r"(a3), "r"(b0), "r"(b1))

// ---------------- kernel 1: LN + QKV + tails + hash + minmax partials ----------
__global__ void __launch_bounds__(768) k_ln_qkv(
    const float* __restrict__ x, const float* __restrict__ n1w,
    const float* __restrict__ n1b, const float* __restrict__ wq,
    const float* __restrict__ wk, const float* __restrict__ wv,
    const float* __restrict__ wr, const float* __restrict__ coords,
    const float* __restrict__ alpha) {
    __shared__ float xs[128 * QSTR];
    __shared__ float Msm0[32 * 24];
    __shared__ float Msm1[32 * 24];
    __shared__ float sw[24];
    __shared__ float part_mn[24][8];
    __shared__ float part_mx[24][8];
    int base = blockIdx.x * 128;
    int tid = threadIdx.x;

    if (tid < CHN) {
        int h = tid / 3, r = tid % 3;
        float qw = 0.f;
        for (int k = 0; k < 8; k++) {
            float s = 0.f;
            for (int d = 0; d < 32; d++) s += wr[(h * 32 + d) * 24 + r * 8 + k];
            qw += expf(fminf(s, 50.f));
        }
        sw[tid] = sqrtf(2.f * qw);
    }
    {
        int ch = tid >> 5, e = tid & 31;
        int c = ch >> 3, h = ch & 7;
        float mq = 0.f, mk = 0.f;
        const float* wqr = wq + e * 256 + h * 32;
        const float* wkr = wk + e * 256 + h * 32;
        const float* al = alpha + h * 105 + c;
#pragma unroll 8
        for (int d = 0; d < 32; d++) {
            float a = al[d * 3];
            mq += wqr[d] * a;
            mk += wkr[d] * a;
        }
        Msm0[e * 24 + ch] = mq;
        Msm1[e * 24 + ch] = mk;
    }
    __syncthreads();

    if (tid < 128) {
        int n = base + tid;
        float r[32];
        const float4* xr = (const float4*)(x + (size_t)n * 32);
#pragma unroll
        for (int u = 0; u < 8; u++) {
            float4 v4 = xr[u];
            r[4 * u] = v4.x; r[4 * u + 1] = v4.y; r[4 * u + 2] = v4.z; r[4 * u + 3] = v4.w;
        }
        float mu = 0.f;
#pragma unroll
        for (int d = 0; d < 32; d++) mu += r[d];
        mu *= (1.0f / 32.0f);
        float var = 0.f;
#pragma unroll
        for (int d = 0; d < 32; d++) { float dd = r[d] - mu; var += dd * dd; }
        var *= (1.0f / 32.0f);
        float rs = rsqrtf(var + 1e-5f);
#pragma unroll
        for (int d = 0; d < 32; d++)
            xs[tid * QSTR + d] = (r[d] - mu) * rs * n1w[d] + n1b[d];
    }
    __syncthreads();

    {
        int proj = tid >> 8, jj = tid & 255;
        const float* W = (proj == 0) ? wq : (proj == 1) ? wk : wv;
        ull wpk[16];
#pragma unroll
        for (int d = 0; d < 16; d++)
            wpk[d] = pk2(W[(2 * d) * 256 + jj], W[(2 * d + 1) * 256 + jj]);
        int h = jj >> 5, d0 = jj & 31;
        float* dst;
        int stride;
        if (proj == 0) { dst = g_qhat; stride = QSTR; }
        else if (proj == 1) { dst = g_khat; stride = QSTR; }
        else { dst = g_v; stride = DH; }
        for (int r = 0; r < 128; r++) {
            const float4* xr = (const float4*)(xs + r * QSTR);
            ull a0 = 0, a1 = 0;
#pragma unroll
            for (int u = 0; u < 8; u++) {
                float4 v4 = xr[u];
                a0 = f2fma(lo2(v4), wpk[2 * u], a0);
                a1 = f2fma(hi2(v4), wpk[2 * u + 1], a1);
            }
            float s0, s1;
            upk(f2add(a0, a1), s0, s1);
            dst[((size_t)h * NPTS + (base + r)) * stride + d0] = s0 + s1;
        }
    }
    if (tid < 128) {
        int n = base + tid;
        float c0 = coords[n * 3], c1 = coords[n * 3 + 1], c2 = coords[n * 3 + 2];
#pragma unroll
        for (int h = 0; h < 8; h++) {
            float4 tail = make_float4(sw[h * 3] * c0, sw[h * 3 + 1] * c1,
                                      sw[h * 3 + 2] * c2, 0.f);
            *(float4*)(g_qhat + ((size_t)h * NPTS + n) * QSTR + 32) = tail;
            *(float4*)(g_khat + ((size_t)h * NPTS + n) * QSTR + 32) = tail;
        }
    }
    {
        int row = tid & 127;
        int slot = tid >> 7;
        int half = slot >= 3;
        int c = half ? slot - 3 : slot;
        int n = base + row;
        float xr[32];
        const float4* xrow = (const float4*)(xs + row * QSTR);
#pragma unroll
        for (int u = 0; u < 8; u++) ((float4*)xr)[u] = xrow[u];
        float c0 = coords[n * 3], c1 = coords[n * 3 + 1], c2 = coords[n * 3 + 2];
        const float* M = half ? Msm1 : Msm0;
        float acc[8];
#pragma unroll
        for (int h = 0; h < 8; h++) acc[h] = 0.f;
#pragma unroll 8
        for (int e = 0; e < 32; e++) {
            float xv = xr[e];
            const float* Mr = M + e * 24 + c * 8;
#pragma unroll
            for (int h = 0; h < 8; h++) acc[h] += xv * Mr[h];
        }
        float* dst = half ? g_kh : g_qh;
#pragma unroll
        for (int h = 0; h < 8; h++) {
            float sr0 = sw[h * 3] * c0, sr1 = sw[h * 3 + 1] * c1, sr2 = sw[h * 3 + 2] * c2;
            const float* al = alpha + h * 105 + c;
            acc[h] += sr0 * al[96] + sr1 * al[99] + sr2 * al[102];
            dst[(size_t)(c * 8 + h) * NPTS + n] = acc[h];
        }
        int rw = row >> 5;
#pragma unroll
        for (int h = 0; h < 8; h++) {
            float mn = acc[h], mx = acc[h];
#pragma unroll
            for (int o = 16; o > 0; o >>= 1) {
                mn = fminf(mn, __shfl_xor_sync(0xFFFFFFFFu, mn, o));
                mx = fmaxf(mx, __shfl_xor_sync(0xFFFFFFFFu, mx, o));
            }
            if ((tid & 31) == 0) {
                part_mn[c * 8 + h][half * 4 + rw] = mn;
                part_mx[c * 8 + h][half * 4 + rw] = mx;
            }
        }
    }
    __syncthreads();
    if (tid < CHN) {
        float mn = part_mn[tid][0], mx = part_mx[tid][0];
#pragma unroll
        for (int i = 1; i < 8; i++) {
            mn = fminf(mn, part_mn[tid][i]);
            mx = fmaxf(mx, part_mx[tid][i]);
        }
        g_pmn[tid * 256 + blockIdx.x] = encf(mn);
        g_pmx[tid * 256 + blockIdx.x] = encf(mx);
    }
}

// ---------------- bitonic sort primitives ----------------
template<int J>
__device__ __forceinline__ void shflp8(ull* r, int ibase, int l, int k_) {
#pragma unroll
    for (int s = 0; s < 8; s++) {
        int i = ibase + s * 32;
        bool up = ((i & k_) == 0);
        ull o = __shfl_xor_sync(0xFFFFFFFFu, r[s], J);
        bool kmin = (((l & J) == 0) == up);
        ull lo_ = (r[s] < o) ? r[s] : o;
        ull hi_ = (r[s] < o) ? o : r[s];
        r[s] = kmin ? lo_ : hi_;
    }
}
template<int JS>
__device__ __forceinline__ void slotp8(ull* r, int ibase, int k_) {
#pragma unroll
    for (int s = 0; s < 8; s++) {
        if (!(s & JS)) {
            int sp = s | JS;
            int i = ibase + s * 32;
            bool up = ((i & k_) == 0);
            if ((r[s] > r[sp]) == up) { ull t2 = r[s]; r[s] = r[sp]; r[sp] = t2; }
        }
    }
}
__device__ __forceinline__ void regpasses8(ull* r, int ibase, int l, int k_) {
    int half = k_ >> 1;
    if (half >= 128) slotp8<4>(r, ibase, k_);
    if (half >= 64)  slotp8<2>(r, ibase, k_);
    if (half >= 32)  slotp8<1>(r, ibase, k_);
    if (half >= 16)  shflp8<16>(r, ibase, l, k_);
    if (half >= 8)   shflp8<8>(r, ibase, l, k_);
    if (half >= 4)   shflp8<4>(r, ibase, l, k_);
    if (half >= 2)   shflp8<2>(r, ibase, l, k_);
    shflp8<1>(r, ibase, l, k_);
}
__device__ __forceinline__ void smem_pass8k(ull* s, int k_, int j_, int tid) {
#pragma unroll
    for (int p = 0; p < 4; p++) {
        int t = tid + p * 1024;
        int i = ((t & ~(j_ - 1)) << 1) | (t & (j_ - 1));
        bool up = ((i & k_) == 0);
        ull a = s[i], b = s[i + j_];
        if ((a > b) == up) { s[i] = b; s[i + j_] = a; }
    }
}

__global__ void __launch_bounds__(1024) k_sort8k(const int* __restrict__ shifts) {
    extern __shared__ ull s8[];
    __shared__ unsigned redn[8], redx[8];
    __shared__ float s_hsv;
    size_t base = (size_t)blockIdx.x * 8192;
    int tid = threadIdx.x;
    int w = tid >> 5, l = tid & 31;
    int ibase = w * 256 + l;

    bool isQ = (base < (size_t)CHN * NPTS);
    size_t hoff = isQ ? base : base - (size_t)CHN * NPTS;
    int seg = (int)(hoff >> 15);

    if (tid < 256) {
        unsigned umn = g_pmn[seg * 256 + tid];
        unsigned umx = g_pmx[seg * 256 + tid];
        unsigned a = __reduce_min_sync(0xFFFFFFFFu, umn);
        unsigned b = __reduce_max_sync(0xFFFFFFFFu, umx);
        if ((tid & 31) == 0) { redn[tid >> 5] = a; redx[tid >> 5] = b; }
    }
    __syncthreads();
    if (tid == 0) {
        unsigned a = redn[0], b = redx[0];
#pragma unroll
        for (int i = 1; i < 8; i++) {
            if (redn[i] < a) a = redn[i];
            if (redx[i] > b) b = redx[i];
        }
        s_hsv = decf(b) - decf(a);
    }
    __syncthreads();
    float hsv = s_hsv;
    const float* hsrc = isQ ? g_qh : g_kh;
    ull r[8];
#pragma unroll
    for (int s_ = 0; s_ < 8; s_++) {
        size_t t = hoff + ibase + s_ * 32;
        float off = __fmul_rn((float)shifts[t], hsv);
        r[s_] = ((ull)encf(__fadd_rn(hsrc[t], off)) << 32) | (unsigned)(t & (NPTS - 1));
    }
    for (int k_ = 2; k_ <= 256; k_ <<= 1) regpasses8(r, ibase, l, k_);
    for (int k_ = 512; k_ <= 8192; k_ <<= 1) {
#pragma unroll
        for (int s_ = 0; s_ < 8; s_++) s8[ibase + s_ * 32] = r[s_];
        __syncthreads();
        for (int j_ = k_ >> 1; j_ >= 256; j_ >>= 1) {
            smem_pass8k(s8, k_, j_, tid);
            __syncthreads();
        }
#pragma unroll
        for (int s_ = 0; s_ < 8; s_++) r[s_] = s8[ibase + s_ * 32];
        __syncthreads();
        regpasses8(r, ibase, l, k_);
    }
#pragma unroll
    for (int s_ = 0; s_ < 8; s_++) g_keys[base + ibase + s_ * 32] = r[s_];
}

__global__ void __launch_bounds__(256) k_mergepath(int L, int dir) {
    const ull* __restrict__ src = dir ? g_keys2 : g_keys;
    ull* __restrict__ dst = dir ? g_keys : g_keys2;
    size_t outbase = (size_t)blockIdx.x * 4096 + (size_t)threadIdx.x * 16;
    size_t pairBase = outbase & ~((size_t)(2 * L) - 1);
    const ull* A = src + pairBase;
    const ull* B = A + L;
    int p0 = (int)(outbase - pairBase);
    int lo = p0 > L ? p0 - L : 0;
    int hi = p0 < L ? p0 : L;
    while (lo < hi) {
        int m = (lo + hi) >> 1;
        if (A[m] <= B[p0 - 1 - m]) lo = m + 1; else hi = m;
    }
    int i = lo, j = p0 - lo;
    ull* d = dst + pairBase + p0;
    ull a = (i < L) ? A[i] : ~0ull;
    ull b = (j < L) ? B[j] : ~0ull;
#pragma unroll
    for (int t = 0; t < 16; t++) {
        bool takeA = (a <= b);
        d[t] = takeA ? a : b;
        if (takeA) { i++; a = (i < L) ? A[i] : ~0ull; }
        else       { j++; b = (j < L) ? B[j] : ~0ull; }
    }
}

// ---------------- attention: mma.sync tf32, 32x64 warp tiles + packed K ----------------
// smem float offsets
#define OF_Q 0                      // [128][44] = 5632
#define OF_KB 5632                  // 2560 float4 = 10240 floats (packed K hi/lo)
#define OF_V 15872                  // [128][40] tf32 = 5120
#define OF_QSQ 20992                // [128]
#define OF_KSQ 21120                // [128]
#define OF_QIX 21248                // [128] unsigned
#define OF_DEN 21376                // [128] ct1 den partials
#define OF_DEX 21504                // [128][34] ct1 D partials = 4352
#define SMEM_ATTN ((25856) * 4)

__global__ void __launch_bounds__(256) k_attn() {
    extern __shared__ float sm[];
    int seg = blockIdx.y;
    int h = seg & 7;
    int bucket = blockIdx.x;
    int tid = threadIdx.x;

    const ull* kkey = g_keys + ((size_t)(CHN + seg)) * NPTS + bucket * BSZ;
    const ull* qkey = g_keys + (size_t)seg * NPTS + bucket * BSZ;

    if (tid < 128) {
        int r = tid;
        unsigned kidx = (unsigned)kkey[r];
        float tmp[40];
        const float4* kr = (const float4*)(g_khat + ((size_t)h * NPTS + kidx) * QSTR);
#pragma unroll
        for (int u = 0; u < 9; u++) ((float4*)tmp)[u] = kr[u];
        tmp[36] = 0.f; tmp[37] = 0.f; tmp[38] = 0.f; tmp[39] = 0.f;
        float s2 = 0.f;
#pragma unroll
        for (int d = 0; d < 35; d++) s2 += tmp[d] * tmp[d];
        sm[OF_KSQ + r] = -0.5f * s2;
        float4* KB4 = (float4*)(sm + OF_KB);
#pragma unroll
        for (int kt = 0; kt < 5; kt++)
#pragma unroll
            for (int t = 0; t < 4; t++) {
                int d = kt * 8 + t;
                float h0 = tf32r(tmp[d]);
                float h1 = tf32r(tmp[d + 4]);
                KB4[(kt * 4 + t) * 128 + r] =
                    make_float4(h0, h1, tmp[d] - h0, tmp[d + 4] - h1);
            }
        float vv[32];
        const float4* vr = (const float4*)(g_v + ((size_t)h * NPTS + kidx) * DH);
#pragma unroll
        for (int u = 0; u < 8; u++) ((float4*)vv)[u] = vr[u];
#pragma unroll
        for (int d = 0; d < 32; d++) sm[OF_V + r * 40 + d] = tf32r(vv[d]);
    } else {
        int r = tid - 128;
        unsigned qidx = (unsigned)qkey[r];
        ((unsigned*)(sm + OF_QIX))[r] = qidx;
        float tmp[36];
        const float4* qr = (const float4*)(g_qhat + ((size_t)h * NPTS + qidx) * QSTR);
#pragma unroll
        for (int u = 0; u < 9; u++) ((float4*)tmp)[u] = qr[u];
        float s2 = 0.f;
#pragma unroll
        for (int d = 0; d < 35; d++) s2 += tmp[d] * tmp[d];
        sm[OF_QSQ + r] = -0.5f * s2;
#pragma unroll
        for (int d = 0; d < 36; d++) sm[OF_Q + r * 44 + d] = tmp[d];
#pragma unroll
        for (int d = 36; d < 40; d++) sm[OF_Q + r * 44 + d] = 0.f;
    }
    __syncthreads();

    int w = tid >> 5, lane = tid & 31;
    int g = lane >> 2, t = lane & 3;
    int rt = w >> 1, ct = w & 1;
    int rbase = rt * 32;
    const float4* KB4 = (const float4*)(sm + OF_KB);

    float dd[2][4][4];
    float denL[2][2];

#pragma unroll
    for (int m = 0; m < 2; m++) {
        int rA = rbase + m * 16 + g, rB = rA + 8;
        float cc[8][4];
#pragma unroll
        for (int nt = 0; nt < 8; nt++) {
            cc[nt][0] = 0.f; cc[nt][1] = 0.f; cc[nt][2] = 0.f; cc[nt][3] = 0.f;
        }
        // S tile (32 rows x 64 cols per warp), 3xTF32
#pragma unroll
        for (int kt = 0; kt < 5; kt++) {
            float a0f = sm[OF_Q + rA * 44 + kt * 8 + t];
            float a1f = sm[OF_Q + rB * 44 + kt * 8 + t];
            float a2f = sm[OF_Q + rA * 44 + kt * 8 + t + 4];
            float a3f = sm[OF_Q + rB * 44 + kt * 8 + t + 4];
            float h0 = tf32r(a0f), h1 = tf32r(a1f), h2 = tf32r(a2f), h3 = tf32r(a3f);
            uint32_t ah0 = __float_as_uint(h0), ah1 = __float_as_uint(h1);
            uint32_t ah2 = __float_as_uint(h2), ah3 = __float_as_uint(h3);
            uint32_t al0 = __float_as_uint(a0f - h0), al1 = __float_as_uint(a1f - h1);
            uint32_t al2 = __float_as_uint(a2f - h2), al3 = __float_as_uint(a3f - h3);
#pragma unroll
            for (int nt = 0; nt < 8; nt++) {
                float4 kb = KB4[(kt * 4 + t) * 128 + ct * 64 + nt * 8 + g];
                uint32_t bh0 = __float_as_uint(kb.x), bh1 = __float_as_uint(kb.y);
                uint32_t bl0 = __float_as_uint(kb.z), bl1 = __float_as_uint(kb.w);
                MMA_TF32(cc[nt], ah0, ah1, ah2, ah3, bh0, bh1);
                MMA_TF32(cc[nt], ah0, ah1, ah2, ah3, bl0, bl1);
                MMA_TF32(cc[nt], al0, al1, al2, al3, bh0, bh1);
            }
        }
        // exp + partial den over this warp's 64 cols
        float qsqA = sm[OF_QSQ + rA], qsqB = sm[OF_QSQ + rB];
        float dA = 0.f, dB = 0.f;
#pragma unroll
        for (int nt = 0; nt < 8; nt++) {
            int c0 = ct * 64 + nt * 8 + 2 * t;
            float k0 = sm[OF_KSQ + c0], k1 = sm[OF_KSQ + c0 + 1];
            float e0 = __expf(fminf(cc[nt][0] + qsqA + k0, 0.f));
            float e1 = __expf(fminf(cc[nt][1] + qsqA + k1, 0.f));
            float e2 = __expf(fminf(cc[nt][2] + qsqB + k0, 0.f));
            float e3 = __expf(fminf(cc[nt][3] + qsqB + k1, 0.f));
            dA += e0 + e1; dB += e2 + e3;
            cc[nt][0] = tf32r(e0); cc[nt][1] = tf32r(e1);
            cc[nt][2] = tf32r(e2); cc[nt][3] = tf32r(e3);
        }
        dA += __shfl_xor_sync(0xFFFFFFFFu, dA, 1);
        dA += __shfl_xor_sync(0xFFFFFFFFu, dA, 2);
        dB += __shfl_xor_sync(0xFFFFFFFFu, dB, 1);
        dB += __shfl_xor_sync(0xFFFFFFFFu, dB, 2);
        denL[m][0] = dA; denL[m][1] = dB;

        // PV partial over this warp's 64 k-cols
#pragma unroll
        for (int nv = 0; nv < 4; nv++) {
            dd[m][nv][0] = 0.f; dd[m][nv][1] = 0.f; dd[m][nv][2] = 0.f; dd[m][nv][3] = 0.f;
        }
        int src1 = (lane & ~3) | (t >> 1);
        int src2 = src1 + 2;
        bool odd = (t & 1);
#pragma unroll
        for (int nt = 0; nt < 8; nt++) {
            int ktg = ct * 8 + nt;
            float v00 = __shfl_sync(0xFFFFFFFFu, cc[nt][0], src1);
            float v01 = __shfl_sync(0xFFFFFFFFu, cc[nt][1], src1);
            float v02 = __shfl_sync(0xFFFFFFFFu, cc[nt][2], src1);
            float v03 = __shfl_sync(0xFFFFFFFFu, cc[nt][3], src1);
            float v10 = __shfl_sync(0xFFFFFFFFu, cc[nt][0], src2);
            float v11 = __shfl_sync(0xFFFFFFFFu, cc[nt][1], src2);
            float v12 = __shfl_sync(0xFFFFFFFFu, cc[nt][2], src2);
            float v13 = __shfl_sync(0xFFFFFFFFu, cc[nt][3], src2);
            uint32_t a0 = __float_as_uint(odd ? v01 : v00);
            uint32_t a1 = __float_as_uint(odd ? v03 : v02);
            uint32_t a2 = __float_as_uint(odd ? v11 : v10);
            uint32_t a3 = __float_as_uint(odd ? v13 : v12);
#pragma unroll
            for (int nv = 0; nv < 4; nv++) {
                uint32_t b0 = __float_as_uint(sm[OF_V + (ktg * 8 + t) * 40 + nv * 8 + g]);
                uint32_t b1 = __float_as_uint(sm[OF_V + (ktg * 8 + t + 4) * 40 + nv * 8 + g]);
                MMA_TF32(dd[m][nv], a0, a1, a2, a3, b0, b1);
            }
        }
        // ct=1 publishes partials
        if (ct == 1) {
            if (t == 0) {
                sm[OF_DEN + rA] = dA;
                sm[OF_DEN + rB] = dB;
            }
#pragma unroll
            for (int nv = 0; nv < 4; nv++) {
                int colb = nv * 8 + 2 * t;
                *(float2*)(sm + OF_DEX + rA * 34 + colb) = make_float2(dd[m][nv][0], dd[m][nv][1]);
                *(float2*)(sm + OF_DEX + rB * 34 + colb) = make_float2(dd[m][nv][2], dd[m][nv][3]);
            }
        }
    }
    __syncthreads();

    if (ct == 0) {
#pragma unroll
        for (int m = 0; m < 2; m++) {
            int rA = rbase + m * 16 + g, rB = rA + 8;
            unsigned qA = ((unsigned*)(sm + OF_QIX))[rA];
            unsigned qB = ((unsigned*)(sm + OF_QIX))[rB];
            if (t == 0) {
                g_dscr[(size_t)seg * NPTS + qA] = denL[m][0] + sm[OF_DEN + rA];
                g_dscr[(size_t)seg * NPTS + qB] = denL[m][1] + sm[OF_DEN + rB];
            }
            float* odA = g_oscr + ((size_t)seg * NPTS + qA) * DH;
            float* odB = g_oscr + ((size_t)seg * NPTS + qB) * DH;
#pragma unroll
            for (int nv = 0; nv < 4; nv++) {
                int colb = nv * 8 + 2 * t;
                float2 pA = *(float2*)(sm + OF_DEX + rA * 34 + colb);
                float2 pB = *(float2*)(sm + OF_DEX + rB * 34 + colb);
                *(float2*)(odA + colb) = make_float2(dd[m][nv][0] + pA.x, dd[m][nv][1] + pA.y);
                *(float2*)(odB + colb) = make_float2(dd[m][nv][2] + pB.x, dd[m][nv][3] + pB.y);
            }
        }
    }
}

// ---------------- epilogue: combine + out-proj + residual + LN2 + FF + residual ----------
__global__ void __launch_bounds__(128) k_epilogue(
    const float* __restrict__ x, const float* __restrict__ ow,
    const float* __restrict__ ob, const float* __restrict__ n2w,
    const float* __restrict__ n2b, const float* __restrict__ f1w,
    const float* __restrict__ f1b, const float* __restrict__ f2w,
    const float* __restrict__ f2b, float* __restrict__ out) {
    __shared__ float ws[256 * 32];
    __shared__ float f1sT[32 * 32];
    __shared__ float f2s[32 * 32];
    __shared__ float cs[32 * 5];
    int tid = threadIdx.x;
    for (int i = tid; i < 8192; i += 128) ws[i] = ow[i];
    for (int i = tid; i < 1024; i += 128) {
        f1sT[(i & 31) * 32 + (i >> 5)] = f1w[i];
        f2s[i] = f2w[i];
    }
    if (tid < 32) {
        cs[tid] = ob[tid]; cs[32 + tid] = n2w[tid]; cs[64 + tid] = n2b[tid];
        cs[96 + tid] = f1b[tid]; cs[128 + tid] = f2b[tid];
    }
    __syncthreads();
    int n = blockIdx.x * 128 + tid;

    ull acc2[16];
#pragma unroll
    for (int p = 0; p < 16; p++) acc2[p] = pk2(cs[2 * p], cs[2 * p + 1]);

#pragma unroll 1
    for (int h = 0; h < 8; h++) {
        float den = g_dscr[(size_t)h * NPTS + n] +
                    g_dscr[(size_t)(8 + h) * NPTS + n] +
                    g_dscr[(size_t)(16 + h) * NPTS + n] + 3e-20f;
        float inv = 1.0f / den;
        const float4* oa = (const float4*)(g_oscr + ((size_t)h * NPTS + n) * DH);
        const float4* obp = (const float4*)(g_oscr + ((size_t)(8 + h) * NPTS + n) * DH);
        const float4* oc = (const float4*)(g_oscr + ((size_t)(16 + h) * NPTS + n) * DH);
#pragma unroll
        for (int p4 = 0; p4 < 8; p4++) {
            float4 a4 = oa[p4], b4 = obp[p4], c4 = oc[p4];
            float av[4];
            av[0] = (a4.x + b4.x + c4.x) * inv;
            av[1] = (a4.y + b4.y + c4.y) * inv;
            av[2] = (a4.z + b4.z + c4.z) * inv;
            av[3] = (a4.w + b4.w + c4.w) * inv;
            int j0 = h * 32 + p4 * 4;
#pragma unroll
            for (int u = 0; u < 4; u++) {
                ull ad = pk2(av[u], av[u]);
                const float4* wr2 = (const float4*)(ws + (j0 + u) * 32);
#pragma unroll
                for (int p = 0; p < 8; p++) {
                    float4 w4 = wr2[p];
                    acc2[2 * p] = f2fma(ad, lo2(w4), acc2[2 * p]);
                    acc2[2 * p + 1] = f2fma(ad, hi2(w4), acc2[2 * p + 1]);
                }
            }
        }
    }
    float acc[32];
#pragma unroll
    for (int p = 0; p < 16; p++) upk(acc2[p], acc[2 * p], acc[2 * p + 1]);

    float x2[32];
    const float4* xr = (const float4*)(x + (size_t)n * 32);
#pragma unroll
    for (int u = 0; u < 8; u++) {
        float4 xv = xr[u];
        x2[4 * u] = xv.x + acc[4 * u];
        x2[4 * u + 1] = xv.y + acc[4 * u + 1];
        x2[4 * u + 2] = xv.z + acc[4 * u + 2];
        x2[4 * u + 3] = xv.w + acc[4 * u + 3];
    }
    float mu = 0.f;
#pragma unroll
    for (int d = 0; d < 32; d++) mu += x2[d];
    mu *= (1.0f / 32.0f);
    float var = 0.f;
#pragma unroll
    for (int d = 0; d < 32; d++) { float dd = x2[d] - mu; var += dd * dd; }
    var *= (1.0f / 32.0f);
    float rs = rsqrtf(var + 1e-5f);
    float xn2[32];
#pragma unroll
    for (int d = 0; d < 32; d++)
        xn2[d] = (x2[d] - mu) * rs * cs[32 + d] + cs[64 + d];
    ull xp[16];
#pragma unroll
    for (int u = 0; u < 16; u++) xp[u] = pk2(xn2[2 * u], xn2[2 * u + 1]);
    float h1[32];
#pragma unroll 4
    for (int jj = 0; jj < 32; jj++) {
        const float4* fr = (const float4*)(f1sT + jj * 32);
        ull a0 = 0ull, a1 = 0ull;
#pragma unroll
        for (int u = 0; u < 8; u++) {
            float4 v4 = fr[u];
            a0 = f2fma(lo2(v4), xp[2 * u], a0);
            a1 = f2fma(hi2(v4), xp[2 * u + 1], a1);
        }
        float s0, s1;
        upk(f2add(a0, a1), s0, s1);
        float t2 = cs[96 + jj] + s0 + s1;
        h1[jj] = t2 / (1.0f + __expf(-t2));
    }
    ull o2[16];
#pragma unroll
    for (int p = 0; p < 16; p++) o2[p] = pk2(cs[128 + 2 * p], cs[128 + 2 * p + 1]);
#pragma unroll 4
    for (int jj = 0; jj < 32; jj++) {
        ull hd = pk2(h1[jj], h1[jj]);
        const float4* fr = (const float4*)(f2s + jj * 32);
#pragma unroll
        for (int p = 0; p < 8; p++) {
            float4 v4 = fr[p];
            o2[2 * p] = f2fma(hd, lo2(v4), o2[2 * p]);
            o2[2 * p + 1] = f2fma(hd, hi2(v4), o2[2 * p + 1]);
        }
    }
    float o[32];
#pragma unroll
    for (int p = 0; p < 16; p++) upk(o2[p], o[2 * p], o[2 * p + 1]);
    float4* orow = (float4*)(out + (size_t)n * 32);
#pragma unroll
    for (int u = 0; u < 8; u++)
        orow[u] = make_float4(x2[4 * u] + o[4 * u], x2[4 * u + 1] + o[4 * u + 1],
                              x2[4 * u + 2] + o[4 * u + 2], x2[4 * u + 3] + o[4 * u + 3]);
}

// ---------------- launcher ----------------
extern "C" void kernel_launch(void* const* d_in, const int* in_sizes, int n_in,
                              void* d_out, int out_size) {
    const float* x = (const float*)d_in[0];
    const float* coords = (const float*)d_in[1];
    const int* shifts = (const int*)d_in[2];
    const float* n1w = (const float*)d_in[3];
    const float* n1b = (const float*)d_in[4];
    const float* wq = (const float*)d_in[5];
    const float* wk = (const float*)d_in[6];
    const float* wv = (const float*)d_in[7];
    const float* wr = (const float*)d_in[8];
    const float* alpha = (const float*)d_in[9];
    const float* ow = (const float*)d_in[10];
    const float* ob = (const float*)d_in[11];
    const float* n2w = (const float*)d_in[12];
    const float* n2b = (const float*)d_in[13];
    const float* f1w = (const float*)d_in[14];
    const float* f1b = (const float*)d_in[15];
    const float* f2w = (const float*)d_in[16];
    const float* f2b = (const float*)d_in[17];
    float* out = (float*)d_out;

    cudaFuncSetAttribute(k_sort8k, cudaFuncAttributeMaxDynamicSharedMemorySize, 65536);
    cudaFuncSetAttribute(k_attn, cudaFuncAttributeMaxDynamicSharedMemorySize, SMEM_ATTN);

    k_ln_qkv<<<NPTS / 128, 768>>>(x, n1w, n1b, wq, wk, wv, wr, coords, alpha);

    const int TOT = 2 * CHN * NPTS;
    k_sort8k<<<TOT / 8192, 1024, 65536>>>(shifts);
    k_mergepath<<<TOT / 4096, 256>>>(8192, 0);    // keys  -> keys2 (16384 runs)
    k_mergepath<<<TOT / 4096, 256>>>(16384, 1);   // keys2 -> keys  (32768 runs)

    k_attn<<<dim3(NBK, CHN), 256, SMEM_ATTN>>>();
    k_epilogue<<<NPTS / 128, 128>>>(x, ow, ob, n2w, n2b, f1w, f1b, f2w, f2b, out);
}

// round 17
// speedup vs baseline: 1.3828x; 1.3828x over previous
#include <cuda_runtime.h>
#include <cstdint>

#define NPTS 32768
#define DH 32
#define NH 8
#define BSZ 128
#define NBK 256
#define CHN 24
#define QSTR 36

typedef unsigned long long ull;

__device__ float g_qhat[(size_t)NH * NPTS * QSTR];
__device__ float g_khat[(size_t)NH * NPTS * QSTR];
__device__ float g_v[(size_t)NH * NPTS * DH];
__device__ float g_qh[(size_t)CHN * NPTS];
__device__ float g_kh[(size_t)CHN * NPTS];
__device__ ull   g_keys[(size_t)2 * CHN * NPTS];
__device__ ull   g_keys2[(size_t)2 * CHN * NPTS];
__device__ unsigned g_pmn[CHN * 256];
__device__ unsigned g_pmx[CHN * 256];
__device__ float g_oscr[(size_t)CHN * NPTS * DH];
__device__ float g_dscr[(size_t)CHN * NPTS];

// ---------------- f32x2 helpers ----------------
__device__ __forceinline__ ull pk2(float a, float b) {
    ull r; asm("mov.b64 %0, {%1, %2};" : "=l"(r) : "f"(a), "f"(b)); return r;
}
__device__ __forceinline__ void upk(ull p, float& a, float& b) {
    asm("mov.b64 {%0, %1}, %2;" : "=f"(a), "=f"(b) : "l"(p));
}
__device__ __forceinline__ ull f2fma(ull a, ull b, ull c) {
    ull d; asm("fma.rn.f32x2 %0, %1, %2, %3;" : "=l"(d) : "l"(a), "l"(b), "l"(c)); return d;
}
__device__ __forceinline__ ull f2add(ull a, ull b) {
    ull d; asm("add.rn.f32x2 %0, %1, %2;" : "=l"(d) : "l"(a), "l"(b)); return d;
}
__device__ __forceinline__ ull lo2(float4 v) { return pk2(v.x, v.y); }
__device__ __forceinline__ ull hi2(float4 v) { return pk2(v.z, v.w); }

__device__ __forceinline__ unsigned encf(float f) {
    unsigned u = __float_as_uint(f);
    return (u & 0x80000000u) ? ~u : (u | 0x80000000u);
}
__device__ __forceinline__ float decf(unsigned u) {
    return (u & 0x80000000u) ? __uint_as_float(u ^ 0x80000000u)
                             : __uint_as_float(~u);
}
__device__ __forceinline__ float tf32r(float x) {
    uint32_t u; asm("cvt.rna.tf32.f32 %0, %1;" : "=r"(u) : "f"(x));
    return __uint_as_float(u);
}
#define MMA_TF32(c, a0, a1, a2, a3, b0, b1) \
    asm volatile("mma.sync.aligned.m16n8k8.row.col.f32.tf32.tf32.f32 " \
        "{%0,%1,%2,%3}, {%4,%5,%6,%7}, {%8,%9}, {%0,%1,%2,%3};" \
        : "+f"((c)[0]), "+f"((c)[1]), "+f"((c)[2]), "+f"((c)[3]) \
        : "r"(a0), "r"(a1), "r"(a2), "r"(a3), "r"(b0), "r"(b1))

// ---------------- kernel 1: LN + QKV + tails + hash + minmax partials ----------
__global__ void __launch_bounds__(768) k_ln_qkv(
    const float* __restrict__ x, const float* __restrict__ n1w,
    const float* __restrict__ n1b, const float* __restrict__ wq,
    const float* __restrict__ wk, const float* __restrict__ wv,
    const float* __restrict__ wr, const float* __restrict__ coords,
    const float* __restrict__ alpha) {
    __shared__ float xs[128 * QSTR];
    __shared__ float Msm0[32 * 24];
    __shared__ float Msm1[32 * 24];
    __shared__ float sw[24];
    __shared__ float part_mn[24][8];
    __shared__ float part_mx[24][8];
    int base = blockIdx.x * 128;
    int tid = threadIdx.x;

    if (tid < CHN) {
        int h = tid / 3, r = tid % 3;
        float qw = 0.f;
        for (int k = 0; k < 8; k++) {
            float s = 0.f;
            for (int d = 0; d < 32; d++) s += wr[(h * 32 + d) * 24 + r * 8 + k];
            qw += expf(fminf(s, 50.f));
        }
        sw[tid] = sqrtf(2.f * qw);
    }
    {
        int ch = tid >> 5, e = tid & 31;
        int c = ch >> 3, h = ch & 7;
        float mq = 0.f, mk = 0.f;
        const float* wqr = wq + e * 256 + h * 32;
        const float* wkr = wk + e * 256 + h * 32;
        const float* al = alpha + h * 105 + c;
#pragma unroll 8
        for (int d = 0; d < 32; d++) {
            float a = al[d * 3];
            mq += wqr[d] * a;
            mk += wkr[d] * a;
        }
        Msm0[e * 24 + ch] = mq;
        Msm1[e * 24 + ch] = mk;
    }
    __syncthreads();

    if (tid < 128) {
        int n = base + tid;
        float r[32];
        const float4* xr = (const float4*)(x + (size_t)n * 32);
#pragma unroll
        for (int u = 0; u < 8; u++) {
            float4 v4 = xr[u];
            r[4 * u] = v4.x; r[4 * u + 1] = v4.y; r[4 * u + 2] = v4.z; r[4 * u + 3] = v4.w;
        }
        float mu = 0.f;
#pragma unroll
        for (int d = 0; d < 32; d++) mu += r[d];
        mu *= (1.0f / 32.0f);
        float var = 0.f;
#pragma unroll
        for (int d = 0; d < 32; d++) { float dd = r[d] - mu; var += dd * dd; }
        var *= (1.0f / 32.0f);
        float rs = rsqrtf(var + 1e-5f);
#pragma unroll
        for (int d = 0; d < 32; d++)
            xs[tid * QSTR + d] = (r[d] - mu) * rs * n1w[d] + n1b[d];
    }
    __syncthreads();

    {
        int proj = tid >> 8, jj = tid & 255;
        const float* W = (proj == 0) ? wq : (proj == 1) ? wk : wv;
        ull wpk[16];
#pragma unroll
        for (int d = 0; d < 16; d++)
            wpk[d] = pk2(W[(2 * d) * 256 + jj], W[(2 * d + 1) * 256 + jj]);
        int h = jj >> 5, d0 = jj & 31;
        float* dst;
        int stride;
        if (proj == 0) { dst = g_qhat; stride = QSTR; }
        else if (proj == 1) { dst = g_khat; stride = QSTR; }
        else { dst = g_v; stride = DH; }
        for (int r = 0; r < 128; r++) {
            const float4* xr = (const float4*)(xs + r * QSTR);
            ull a0 = 0, a1 = 0;
#pragma unroll
            for (int u = 0; u < 8; u++) {
                float4 v4 = xr[u];
                a0 = f2fma(lo2(v4), wpk[2 * u], a0);
                a1 = f2fma(hi2(v4), wpk[2 * u + 1], a1);
            }
            float s0, s1;
            upk(f2add(a0, a1), s0, s1);
            dst[((size_t)h * NPTS + (base + r)) * stride + d0] = s0 + s1;
        }
    }
    if (tid < 128) {
        int n = base + tid;
        float c0 = coords[n * 3], c1 = coords[n * 3 + 1], c2 = coords[n * 3 + 2];
#pragma unroll
        for (int h = 0; h < 8; h++) {
            float4 tail = make_float4(sw[h * 3] * c0, sw[h * 3 + 1] * c1,
                                      sw[h * 3 + 2] * c2, 0.f);
            *(float4*)(g_qhat + ((size_t)h * NPTS + n) * QSTR + 32) = tail;
            *(float4*)(g_khat + ((size_t)h * NPTS + n) * QSTR + 32) = tail;
        }
    }
    {
        int row = tid & 127;
        int slot = tid >> 7;
        int half = slot >= 3;
        int c = half ? slot - 3 : slot;
        int n = base + row;
        float xr[32];
        const float4* xrow = (const float4*)(xs + row * QSTR);
#pragma unroll
        for (int u = 0; u < 8; u++) ((float4*)xr)[u] = xrow[u];
        float c0 = coords[n * 3], c1 = coords[n * 3 + 1], c2 = coords[n * 3 + 2];
        const float* M = half ? Msm1 : Msm0;
        float acc[8];
#pragma unroll
        for (int h = 0; h < 8; h++) acc[h] = 0.f;
#pragma unroll 8
        for (int e = 0; e < 32; e++) {
            float xv = xr[e];
            const float* Mr = M + e * 24 + c * 8;
#pragma unroll
            for (int h = 0; h < 8; h++) acc[h] += xv * Mr[h];
        }
        float* dst = half ? g_kh : g_qh;
#pragma unroll
        for (int h = 0; h < 8; h++) {
            float sr0 = sw[h * 3] * c0, sr1 = sw[h * 3 + 1] * c1, sr2 = sw[h * 3 + 2] * c2;
            const float* al = alpha + h * 105 + c;
            acc[h] += sr0 * al[96] + sr1 * al[99] + sr2 * al[102];
            dst[(size_t)(c * 8 + h) * NPTS + n] = acc[h];
        }
        int rw = row >> 5;
#pragma unroll
        for (int h = 0; h < 8; h++) {
            float mn = acc[h], mx = acc[h];
#pragma unroll
            for (int o = 16; o > 0; o >>= 1) {
                mn = fminf(mn, __shfl_xor_sync(0xFFFFFFFFu, mn, o));
                mx = fmaxf(mx, __shfl_xor_sync(0xFFFFFFFFu, mx, o));
            }
            if ((tid & 31) == 0) {
                part_mn[c * 8 + h][half * 4 + rw] = mn;
                part_mx[c * 8 + h][half * 4 + rw] = mx;
            }
        }
    }
    __syncthreads();
    if (tid < CHN) {
        float mn = part_mn[tid][0], mx = part_mx[tid][0];
#pragma unroll
        for (int i = 1; i < 8; i++) {
            mn = fminf(mn, part_mn[tid][i]);
            mx = fmaxf(mx, part_mx[tid][i]);
        }
        g_pmn[tid * 256 + blockIdx.x] = encf(mn);
        g_pmx[tid * 256 + blockIdx.x] = encf(mx);
    }
}

// ---------------- bitonic sort primitives ----------------
template<int J>
__device__ __forceinline__ void shflp8(ull* r, int ibase, int l, int k_) {
#pragma unroll
    for (int s = 0; s < 8; s++) {
        int i = ibase + s * 32;
        bool up = ((i & k_) == 0);
        ull o = __shfl_xor_sync(0xFFFFFFFFu, r[s], J);
        bool kmin = (((l & J) == 0) == up);
        ull lo_ = (r[s] < o) ? r[s] : o;
        ull hi_ = (r[s] < o) ? o : r[s];
        r[s] = kmin ? lo_ : hi_;
    }
}
template<int JS>
__device__ __forceinline__ void slotp8(ull* r, int ibase, int k_) {
#pragma unroll
    for (int s = 0; s < 8; s++) {
        if (!(s & JS)) {
            int sp = s | JS;
            int i = ibase + s * 32;
            bool up = ((i & k_) == 0);
            if ((r[s] > r[sp]) == up) { ull t2 = r[s]; r[s] = r[sp]; r[sp] = t2; }
        }
    }
}
__device__ __forceinline__ void regpasses8(ull* r, int ibase, int l, int k_) {
    int half = k_ >> 1;
    if (half >= 128) slotp8<4>(r, ibase, k_);
    if (half >= 64)  slotp8<2>(r, ibase, k_);
    if (half >= 32)  slotp8<1>(r, ibase, k_);
    if (half >= 16)  shflp8<16>(r, ibase, l, k_);
    if (half >= 8)   shflp8<8>(r, ibase, l, k_);
    if (half >= 4)   shflp8<4>(r, ibase, l, k_);
    if (half >= 2)   shflp8<2>(r, ibase, l, k_);
    shflp8<1>(r, ibase, l, k_);
}
__device__ __forceinline__ void smem_pass8k(ull* s, int k_, int j_, int tid) {
#pragma unroll
    for (int p = 0; p < 4; p++) {
        int t = tid + p * 1024;
        int i = ((t & ~(j_ - 1)) << 1) | (t & (j_ - 1));
        bool up = ((i & k_) == 0);
        ull a = s[i], b = s[i + j_];
        if ((a > b) == up) { s[i] = b; s[i + j_] = a; }
    }
}

__global__ void __launch_bounds__(1024) k_sort8k(const int* __restrict__ shifts) {
    extern __shared__ ull s8[];
    __shared__ unsigned redn[8], redx[8];
    __shared__ float s_hsv;
    size_t base = (size_t)blockIdx.x * 8192;
    int tid = threadIdx.x;
    int w = tid >> 5, l = tid & 31;
    int ibase = w * 256 + l;

    bool isQ = (base < (size_t)CHN * NPTS);
    size_t hoff = isQ ? base : base - (size_t)CHN * NPTS;
    int seg = (int)(hoff >> 15);

    if (tid < 256) {
        unsigned umn = g_pmn[seg * 256 + tid];
        unsigned umx = g_pmx[seg * 256 + tid];
        unsigned a = __reduce_min_sync(0xFFFFFFFFu, umn);
        unsigned b = __reduce_max_sync(0xFFFFFFFFu, umx);
        if ((tid & 31) == 0) { redn[tid >> 5] = a; redx[tid >> 5] = b; }
    }
    __syncthreads();
    if (tid == 0) {
        unsigned a = redn[0], b = redx[0];
#pragma unroll
        for (int i = 1; i < 8; i++) {
            if (redn[i] < a) a = redn[i];
            if (redx[i] > b) b = redx[i];
        }
        s_hsv = decf(b) - decf(a);
    }
    __syncthreads();
    float hsv = s_hsv;
    const float* hsrc = isQ ? g_qh : g_kh;
    ull r[8];
#pragma unroll
    for (int s_ = 0; s_ < 8; s_++) {
        size_t t = hoff + ibase + s_ * 32;
        float off = __fmul_rn((float)shifts[t], hsv);
        r[s_] = ((ull)encf(__fadd_rn(hsrc[t], off)) << 32) | (unsigned)(t & (NPTS - 1));
    }
    for (int k_ = 2; k_ <= 256; k_ <<= 1) regpasses8(r, ibase, l, k_);
    for (int k_ = 512; k_ <= 8192; k_ <<= 1) {
#pragma unroll
        for (int s_ = 0; s_ < 8; s_++) s8[ibase + s_ * 32] = r[s_];
        __syncthreads();
        for (int j_ = k_ >> 1; j_ >= 256; j_ >>= 1) {
            smem_pass8k(s8, k_, j_, tid);
            __syncthreads();
        }
#pragma unroll
        for (int s_ = 0; s_ < 8; s_++) r[s_] = s8[ibase + s_ * 32];
        __syncthreads();
        regpasses8(r, ibase, l, k_);
    }
#pragma unroll
    for (int s_ = 0; s_ < 8; s_++) g_keys[base + ibase + s_ * 32] = r[s_];
}

__global__ void __launch_bounds__(256) k_mergepath(int L, int dir) {
    const ull* __restrict__ src = dir ? g_keys2 : g_keys;
    ull* __restrict__ dst = dir ? g_keys : g_keys2;
    size_t outbase = (size_t)blockIdx.x * 4096 + (size_t)threadIdx.x * 16;
    size_t pairBase = outbase & ~((size_t)(2 * L) - 1);
    const ull* A = src + pairBase;
    const ull* B = A + L;
    int p0 = (int)(outbase - pairBase);
    int lo = p0 > L ? p0 - L : 0;
    int hi = p0 < L ? p0 : L;
    while (lo < hi) {
        int m = (lo + hi) >> 1;
        if (A[m] <= B[p0 - 1 - m]) lo = m + 1; else hi = m;
    }
    int i = lo, j = p0 - lo;
    ull* d = dst + pairBase + p0;
    ull a = (i < L) ? A[i] : ~0ull;
    ull b = (j < L) ? B[j] : ~0ull;
#pragma unroll
    for (int t = 0; t < 16; t++) {
        bool takeA = (a <= b);
        d[t] = takeA ? a : b;
        if (takeA) { i++; a = (i < L) ? A[i] : ~0ull; }
        else       { j++; b = (j < L) ? B[j] : ~0ull; }
    }
}

// ---------------- attention via mma.sync tf32 (R13 tiling + padded packed K) ----------------
// smem float offsets
#define KBSTR 130                   // float4 row stride: 2080B ≡ 32 mod 128 -> conflict-free
#define OF_Q 0                      // [128][44] = 5632
#define OF_KB 5632                  // 20 rows x 130 float4 = 10400 floats
#define OF_V 16032                  // [128][40] tf32 = 5120
#define OF_QSQ 21152                // [128]
#define OF_KSQ 21280                // [128]
#define OF_QIX 21408                // [128] unsigned
#define SMEM_ATTN ((21536) * 4)

__global__ void __launch_bounds__(256) k_attn() {
    extern __shared__ float sm[];
    int seg = blockIdx.y;
    int h = seg & 7;
    int bucket = blockIdx.x;
    int tid = threadIdx.x;

    const ull* kkey = g_keys + ((size_t)(CHN + seg)) * NPTS + bucket * BSZ;
    const ull* qkey = g_keys + (size_t)seg * NPTS + bucket * BSZ;

    if (tid < 128) {
        int r = tid;
        unsigned kidx = (unsigned)kkey[r];
        float tmp[40];
        const float4* kr = (const float4*)(g_khat + ((size_t)h * NPTS + kidx) * QSTR);
#pragma unroll
        for (int u = 0; u < 9; u++) ((float4*)tmp)[u] = kr[u];
        tmp[36] = 0.f; tmp[37] = 0.f; tmp[38] = 0.f; tmp[39] = 0.f;
        float s2 = 0.f;
#pragma unroll
        for (int d = 0; d < 35; d++) s2 += tmp[d] * tmp[d];
        sm[OF_KSQ + r] = -0.5f * s2;
        float4* KB4 = (float4*)(sm + OF_KB);
#pragma unroll
        for (int kt = 0; kt < 5; kt++)
#pragma unroll
            for (int tq = 0; tq < 4; tq++) {
                int d = kt * 8 + tq;
                float h0 = tf32r(tmp[d]);
                float h1 = tf32r(tmp[d + 4]);
                KB4[(kt * 4 + tq) * KBSTR + r] =
                    make_float4(h0, h1, tmp[d] - h0, tmp[d + 4] - h1);
            }
        float vv[32];
        const float4* vr = (const float4*)(g_v + ((size_t)h * NPTS + kidx) * DH);
#pragma unroll
        for (int u = 0; u < 8; u++) ((float4*)vv)[u] = vr[u];
#pragma unroll
        for (int d = 0; d < 32; d++) sm[OF_V + r * 40 + d] = tf32r(vv[d]);
    } else {
        int r = tid - 128;
        unsigned qidx = (unsigned)qkey[r];
        ((unsigned*)(sm + OF_QIX))[r] = qidx;
        float tmp[36];
        const float4* qr = (const float4*)(g_qhat + ((size_t)h * NPTS + qidx) * QSTR);
#pragma unroll
        for (int u = 0; u < 9; u++) ((float4*)tmp)[u] = qr[u];
        float s2 = 0.f;
#pragma unroll
        for (int d = 0; d < 35; d++) s2 += tmp[d] * tmp[d];
        sm[OF_QSQ + r] = -0.5f * s2;
#pragma unroll
        for (int d = 0; d < 36; d++) sm[OF_Q + r * 44 + d] = tmp[d];
#pragma unroll
        for (int d = 36; d < 40; d++) sm[OF_Q + r * 44 + d] = 0.f;
    }
    __syncthreads();

    int w = tid >> 5, lane = tid & 31;
    int g = lane >> 2, t = lane & 3;
    int rA = w * 16 + g, rB = rA + 8;
    const float4* KB4 = (const float4*)(sm + OF_KB);

    float cc[16][4];
#pragma unroll
    for (int nt = 0; nt < 16; nt++) {
        cc[nt][0] = 0.f; cc[nt][1] = 0.f; cc[nt][2] = 0.f; cc[nt][3] = 0.f;
    }

    // S = Q K^T via 3xTF32 (K pre-split, packed float4, padded stride)
#pragma unroll
    for (int kt = 0; kt < 5; kt++) {
        float a0f = sm[OF_Q + rA * 44 + kt * 8 + t];
        float a1f = sm[OF_Q + rB * 44 + kt * 8 + t];
        float a2f = sm[OF_Q + rA * 44 + kt * 8 + t + 4];
        float a3f = sm[OF_Q + rB * 44 + kt * 8 + t + 4];
        float h0 = tf32r(a0f), h1 = tf32r(a1f), h2 = tf32r(a2f), h3 = tf32r(a3f);
        uint32_t ah0 = __float_as_uint(h0), ah1 = __float_as_uint(h1);
        uint32_t ah2 = __float_as_uint(h2), ah3 = __float_as_uint(h3);
        uint32_t al0 = __float_as_uint(a0f - h0), al1 = __float_as_uint(a1f - h1);
        uint32_t al2 = __float_as_uint(a2f - h2), al3 = __float_as_uint(a3f - h3);
#pragma unroll
        for (int nt = 0; nt < 16; nt++) {
            float4 kb = KB4[(kt * 4 + t) * KBSTR + nt * 8 + g];
            uint32_t bh0 = __float_as_uint(kb.x), bh1 = __float_as_uint(kb.y);
            uint32_t bl0 = __float_as_uint(kb.z), bl1 = __float_as_uint(kb.w);
            MMA_TF32(cc[nt], ah0, ah1, ah2, ah3, bh0, bh1);
            MMA_TF32(cc[nt], ah0, ah1, ah2, ah3, bl0, bl1);
            MMA_TF32(cc[nt], al0, al1, al2, al3, bh0, bh1);
        }
    }

    // exp + den, P (tf32-rounded) kept in cc
    float qsqA = sm[OF_QSQ + rA], qsqB = sm[OF_QSQ + rB];
    float denA = 0.f, denB = 0.f;
#pragma unroll
    for (int nt = 0; nt < 16; nt++) {
        int c0 = nt * 8 + 2 * t;
        float k0 = sm[OF_KSQ + c0], k1 = sm[OF_KSQ + c0 + 1];
        float e0 = __expf(fminf(cc[nt][0] + qsqA + k0, 0.f));
        float e1 = __expf(fminf(cc[nt][1] + qsqA + k1, 0.f));
        float e2 = __expf(fminf(cc[nt][2] + qsqB + k0, 0.f));
        float e3 = __expf(fminf(cc[nt][3] + qsqB + k1, 0.f));
        denA += e0 + e1;
        denB += e2 + e3;
        cc[nt][0] = tf32r(e0); cc[nt][1] = tf32r(e1);
        cc[nt][2] = tf32r(e2); cc[nt][3] = tf32r(e3);
    }
    denA += __shfl_xor_sync(0xFFFFFFFFu, denA, 1);
    denA += __shfl_xor_sync(0xFFFFFFFFu, denA, 2);
    denB += __shfl_xor_sync(0xFFFFFFFFu, denB, 1);
    denB += __shfl_xor_sync(0xFFFFFFFFu, denB, 2);

    // D = P V (V already tf32; single pass)
    float dd[4][4];
#pragma unroll
    for (int nv = 0; nv < 4; nv++) {
        dd[nv][0] = 0.f; dd[nv][1] = 0.f; dd[nv][2] = 0.f; dd[nv][3] = 0.f;
    }
    int src1 = (lane & ~3) | (t >> 1);
    int src2 = src1 + 2;
    bool odd = (t & 1);
#pragma unroll
    for (int kt = 0; kt < 16; kt++) {
        float v00 = __shfl_sync(0xFFFFFFFFu, cc[kt][0], src1);
        float v01 = __shfl_sync(0xFFFFFFFFu, cc[kt][1], src1);
        float v02 = __shfl_sync(0xFFFFFFFFu, cc[kt][2], src1);
        float v03 = __shfl_sync(0xFFFFFFFFu, cc[kt][3], src1);
        float v10 = __shfl_sync(0xFFFFFFFFu, cc[kt][0], src2);
        float v11 = __shfl_sync(0xFFFFFFFFu, cc[kt][1], src2);
        float v12 = __shfl_sync(0xFFFFFFFFu, cc[kt][2], src2);
        float v13 = __shfl_sync(0xFFFFFFFFu, cc[kt][3], src2);
        uint32_t a0 = __float_as_uint(odd ? v01 : v00);
        uint32_t a1 = __float_as_uint(odd ? v03 : v02);
        uint32_t a2 = __float_as_uint(odd ? v11 : v10);
        uint32_t a3 = __float_as_uint(odd ? v13 : v12);
#pragma unroll
        for (int nv = 0; nv < 4; nv++) {
            uint32_t bh0 = __float_as_uint(sm[OF_V + (kt * 8 + t) * 40 + nv * 8 + g]);
            uint32_t bh1 = __float_as_uint(sm[OF_V + (kt * 8 + t + 4) * 40 + nv * 8 + g]);
            MMA_TF32(dd[nv], a0, a1, a2, a3, bh0, bh1);
        }
    }

    // write results
    unsigned qA = ((unsigned*)(sm + OF_QIX))[rA];
    unsigned qB = ((unsigned*)(sm + OF_QIX))[rB];
    if (t == 0) {
        g_dscr[(size_t)seg * NPTS + qA] = denA;
        g_dscr[(size_t)seg * NPTS + qB] = denB;
    }
    float* odA = g_oscr + ((size_t)seg * NPTS + qA) * DH;
    float* odB = g_oscr + ((size_t)seg * NPTS + qB) * DH;
#pragma unroll
    for (int nv = 0; nv < 4; nv++) {
        int col = nv * 8 + 2 * t;
        *(float2*)(odA + col) = make_float2(dd[nv][0], dd[nv][1]);
        *(float2*)(odB + col) = make_float2(dd[nv][2], dd[nv][3]);
    }
}

// ---------------- epilogue: combine + out-proj + residual + LN2 + FF + residual ----------
__global__ void __launch_bounds__(128) k_epilogue(
    const float* __restrict__ x, const float* __restrict__ ow,
    const float* __restrict__ ob, const float* __restrict__ n2w,
    const float* __restrict__ n2b, const float* __restrict__ f1w,
    const float* __restrict__ f1b, const float* __restrict__ f2w,
    const float* __restrict__ f2b, float* __restrict__ out) {
    __shared__ float ws[256 * 32];
    __shared__ float f1sT[32 * 32];
    __shared__ float f2s[32 * 32];
    __shared__ float cs[32 * 5];
    int tid = threadIdx.x;
    for (int i = tid; i < 8192; i += 128) ws[i] = ow[i];
    for (int i = tid; i < 1024; i += 128) {
        f1sT[(i & 31) * 32 + (i >> 5)] = f1w[i];
        f2s[i] = f2w[i];
    }
    if (tid < 32) {
        cs[tid] = ob[tid]; cs[32 + tid] = n2w[tid]; cs[64 + tid] = n2b[tid];
        cs[96 + tid] = f1b[tid]; cs[128 + tid] = f2b[tid];
    }
    __syncthreads();
    int n = blockIdx.x * 128 + tid;

    ull acc2[16];
#pragma unroll
    for (int p = 0; p < 16; p++) acc2[p] = pk2(cs[2 * p], cs[2 * p + 1]);

#pragma unroll 1
    for (int h = 0; h < 8; h++) {
        float den = g_dscr[(size_t)h * NPTS + n] +
                    g_dscr[(size_t)(8 + h) * NPTS + n] +
                    g_dscr[(size_t)(16 + h) * NPTS + n] + 3e-20f;
        float inv = 1.0f / den;
        const float4* oa = (const float4*)(g_oscr + ((size_t)h * NPTS + n) * DH);
        const float4* obp = (const float4*)(g_oscr + ((size_t)(8 + h) * NPTS + n) * DH);
        const float4* oc = (const float4*)(g_oscr + ((size_t)(16 + h) * NPTS + n) * DH);
#pragma unroll
        for (int p4 = 0; p4 < 8; p4++) {
            float4 a4 = oa[p4], b4 = obp[p4], c4 = oc[p4];
            float av[4];
            av[0] = (a4.x + b4.x + c4.x) * inv;
            av[1] = (a4.y + b4.y + c4.y) * inv;
            av[2] = (a4.z + b4.z + c4.z) * inv;
            av[3] = (a4.w + b4.w + c4.w) * inv;
            int j0 = h * 32 + p4 * 4;
#pragma unroll
            for (int u = 0; u < 4; u++) {
                ull ad = pk2(av[u], av[u]);
                const float4* wr2 = (const float4*)(ws + (j0 + u) * 32);
#pragma unroll
                for (int p = 0; p < 8; p++) {
                    float4 w4 = wr2[p];
                    acc2[2 * p] = f2fma(ad, lo2(w4), acc2[2 * p]);
                    acc2[2 * p + 1] = f2fma(ad, hi2(w4), acc2[2 * p + 1]);
                }
            }
        }
    }
    float acc[32];
#pragma unroll
    for (int p = 0; p < 16; p++) upk(acc2[p], acc[2 * p], acc[2 * p + 1]);

    float x2[32];
    const float4* xr = (const float4*)(x + (size_t)n * 32);
#pragma unroll
    for (int u = 0; u < 8; u++) {
        float4 xv = xr[u];
        x2[4 * u] = xv.x + acc[4 * u];
        x2[4 * u + 1] = xv.y + acc[4 * u + 1];
        x2[4 * u + 2] = xv.z + acc[4 * u + 2];
        x2[4 * u + 3] = xv.w + acc[4 * u + 3];
    }
    float mu = 0.f;
#pragma unroll
    for (int d = 0; d < 32; d++) mu += x2[d];
    mu *= (1.0f / 32.0f);
    float var = 0.f;
#pragma unroll
    for (int d = 0; d < 32; d++) { float dd = x2[d] - mu; var += dd * dd; }
    var *= (1.0f / 32.0f);
    float rs = rsqrtf(var + 1e-5f);
    float xn2[32];
#pragma unroll
    for (int d = 0; d < 32; d++)
        xn2[d] = (x2[d] - mu) * rs * cs[32 + d] + cs[64 + d];
    ull xp[16];
#pragma unroll
    for (int u = 0; u < 16; u++) xp[u] = pk2(xn2[2 * u], xn2[2 * u + 1]);
    float h1[32];
#pragma unroll 4
    for (int jj = 0; jj < 32; jj++) {
        const float4* fr = (const float4*)(f1sT + jj * 32);
        ull a0 = 0ull, a1 = 0ull;
#pragma unroll
        for (int u = 0; u < 8; u++) {
            float4 v4 = fr[u];
            a0 = f2fma(lo2(v4), xp[2 * u], a0);
            a1 = f2fma(hi2(v4), xp[2 * u + 1], a1);
        }
        float s0, s1;
        upk(f2add(a0, a1), s0, s1);
        float t2 = cs[96 + jj] + s0 + s1;
        h1[jj] = t2 / (1.0f + __expf(-t2));
    }
    ull o2[16];
#pragma unroll
    for (int p = 0; p < 16; p++) o2[p] = pk2(cs[128 + 2 * p], cs[128 + 2 * p + 1]);
#pragma unroll 4
    for (int jj = 0; jj < 32; jj++) {
        ull hd = pk2(h1[jj], h1[jj]);
        const float4* fr = (const float4*)(f2s + jj * 32);
#pragma unroll
        for (int p = 0; p < 8; p++) {
            float4 v4 = fr[p];
            o2[2 * p] = f2fma(hd, lo2(v4), o2[2 * p]);
            o2[2 * p + 1] = f2fma(hd, hi2(v4), o2[2 * p + 1]);
        }
    }
    float o[32];
#pragma unroll
    for (int p = 0; p < 16; p++) upk(o2[p], o[2 * p], o[2 * p + 1]);
    float4* orow = (float4*)(out + (size_t)n * 32);
#pragma unroll
    for (int u = 0; u < 8; u++)
        orow[u] = make_float4(x2[4 * u] + o[4 * u], x2[4 * u + 1] + o[4 * u + 1],
                              x2[4 * u + 2] + o[4 * u + 2], x2[4 * u + 3] + o[4 * u + 3]);
}

// ---------------- launcher ----------------
extern "C" void kernel_launch(void* const* d_in, const int* in_sizes, int n_in,
                              void* d_out, int out_size) {
    const float* x = (const float*)d_in[0];
    const float* coords = (const float*)d_in[1];
    const int* shifts = (const int*)d_in[2];
    const float* n1w = (const float*)d_in[3];
    const float* n1b = (const float*)d_in[4];
    const float* wq = (const float*)d_in[5];
    const float* wk = (const float*)d_in[6];
    const float* wv = (const float*)d_in[7];
    const float* wr = (const float*)d_in[8];
    const float* alpha = (const float*)d_in[9];
    const float* ow = (const float*)d_in[10];
    const float* ob = (const float*)d_in[11];
    const float* n2w = (const float*)d_in[12];
    const float* n2b = (const float*)d_in[13];
    const float* f1w = (const float*)d_in[14];
    const float* f1b = (const float*)d_in[15];
    const float* f2w = (const float*)d_in[16];
    const float* f2b = (const float*)d_in[17];
    float* out = (float*)d_out;

    cudaFuncSetAttribute(k_sort8k, cudaFuncAttributeMaxDynamicSharedMemorySize, 65536);
    cudaFuncSetAttribute(k_attn, cudaFuncAttributeMaxDynamicSharedMemorySize, SMEM_ATTN);

    k_ln_qkv<<<NPTS / 128, 768>>>(x, n1w, n1b, wq, wk, wv, wr, coords, alpha);

    const int TOT = 2 * CHN * NPTS;
    k_sort8k<<<TOT / 8192, 1024, 65536>>>(shifts);
    k_mergepath<<<TOT / 4096, 256>>>(8192, 0);    // keys  -> keys2 (16384 runs)
    k_mergepath<<<TOT / 4096, 256>>>(16384, 1);   // keys2 -> keys  (32768 runs)

    k_attn<<<dim3(NBK, CHN), 256, SMEM_ATTN>>>();
    k_epilogue<<<NPTS / 128, 128>>>(x, ow, ob, n2w, n2b, f1w, f1b, f2w, f2b, out);
}